// round 13
// baseline (speedup 1.0000x reference)
#include <cuda_runtime.h>
#include <cuda_fp16.h>
#include <math.h>
#include <stdint.h>

#define CIN   64
#define COUT  64
#define HH    112
#define WW    112
#define NB    32
#define HW    (HH*WW)            // 12544
#define TOTAL (NB*COUT*HW)       // 25690112
#define MCNT  (NB*HW)            // 401408

// conv tiling: block = 64 co x 256 px (16x16), 8 warps m32xn64, fp16 mma k16
#define TPX 16
#define TPY 16
#define NPOS (18*18)             // 324 halo positions
#define ASTR 72                  // halves per pos row: LDSM conflict-free
#define WSTR 72
#define NWBUF 6                  // cp.async weight ring
#define W_TAP_BYTES (64*WSTR*2)  // 9216 B per tap (pre-padded in gmem)
#define S_ACT_HALVES (NPOS*ASTR)          // 23328
#define SMEM_BYTES (S_ACT_HALVES*2 + NWBUF*W_TAP_BYTES)   // 101952 B -> 2 CTAs/SM

// ---------------- device scratch ----------------
// t1, t2 fp16, channel-pair interleaved: pair pp <-> channels (c0, c0+8),
// c0 = ((pp>>3)<<4) | (pp&7);  g_tXh[(n*32+pp)*HW + pos] = (val_c0, val_c0+8)
__device__ __half2 g_t1h[NB*32*HW];
__device__ __half2 g_t2h[NB*32*HW];
__device__ __half  g_w1[9*64*WSTR];   // [tap][co][slot(ci)], padded to 72
__device__ __half  g_w2[9*64*WSTR];
__device__ float   g_sum[2][COUT];
__device__ float   g_sq[2][COUT];
__device__ float   g_scale[2][COUT];
__device__ float   g_bias[2][COUT];

__device__ __forceinline__ void mma16(float* d, const uint32_t* a, uint32_t b0, uint32_t b1) {
    asm volatile(
        "mma.sync.aligned.m16n8k16.row.col.f32.f16.f16.f32 "
        "{%0,%1,%2,%3}, {%4,%5,%6,%7}, {%8,%9}, {%0,%1,%2,%3};\n"
        : "+f"(d[0]), "+f"(d[1]), "+f"(d[2]), "+f"(d[3])
        : "r"(a[0]), "r"(a[1]), "r"(a[2]), "r"(a[3]), "r"(b0), "r"(b1));
}
__device__ __forceinline__ void ldsm4(uint32_t& r0, uint32_t& r1, uint32_t& r2, uint32_t& r3,
                                      uint32_t addr) {
    asm volatile("ldmatrix.sync.aligned.m8n8.x4.shared.b16 {%0,%1,%2,%3}, [%4];"
        : "=r"(r0), "=r"(r1), "=r"(r2), "=r"(r3) : "r"(addr));
}
__device__ __forceinline__ void cpasync16(uint32_t saddr, const void* gptr) {
    asm volatile("cp.async.cg.shared.global [%0], [%1], 16;" :: "r"(saddr), "l"(gptr));
}

// k slot: pairs (c, c+8) adjacent.  pp = ((ci>>4)<<3)|(ci&7), slot = 2*pp + ((ci>>3)&1)
__device__ __forceinline__ int kslot(int ci) {
    return 2*(((ci >> 4) << 3) | (ci & 7)) + ((ci >> 3) & 1);
}

// ---------------- prep: ternarize + repack(half, k-permuted, padded) ----------
__global__ void prep_kernel(const float* __restrict__ w1,
                            const float* __restrict__ w2) {
    int idx = blockIdx.x * 256 + threadIdx.x;
    if (idx < COUT) {
        g_sum[0][idx] = 0.f; g_sum[1][idx] = 0.f;
        g_sq[0][idx]  = 0.f; g_sq[1][idx]  = 0.f;
    }
    if (idx < 9*64*WSTR) {
        // dst layout: [t][co][s], s in 0..71 (64 data slots + 8 pad)
        int s  = idx % WSTR;
        int co = (idx / WSTR) & 63;
        int t  = idx / (WSTR*64);
        __half v1 = __float2half(0.f), v2 = __float2half(0.f);
        if (s < 64) {
            int pp = s >> 1, hi = s & 1;
            int ci = ((pp >> 3) << 4) | (hi << 3) | (pp & 7);
            int src = (co*64 + ci)*9 + t;
            float a = w1[src];
            v1 = __float2half((fabsf(a) > 0.3f) ? (a > 0.f ? 1.f : -1.f) : 0.f);
            float b = w2[src];
            v2 = __float2half((fabsf(b) > 0.3f) ? (b > 0.f ? 1.f : -1.f) : 0.f);
        }
        g_w1[idx] = v1;
        g_w2[idx] = v2;
    }
}

// ---------------- conv3x3 via 9 shifted 1x1 GEMMs, fp16 mma + ldmatrix ----
// Weights streamed via cp.async into a 6-buffer ring; one barrier per 2 taps.
// PASS 1: in=x(fp32), out=g_t1h.  PASS 2: in=BN1+ht(g_t1h), out=g_t2h (conv + x).
template<int PASS>
__global__ void __launch_bounds__(256, 2) conv_mma_kernel(const float* __restrict__ x) {
    extern __shared__ __half smem_h[];
    __half* s_act = smem_h;                       // [pos][slot] stride 72
    __shared__ float s_s[COUT], s_b[COUT];
    __shared__ float s_sum[COUT], s_sq[COUT];

    const __half* wrep = (PASS == 1) ? g_w1 : g_w2;

    const int tid  = threadIdx.x;
    const int lane = tid & 31;
    const int wid  = tid >> 5;
    const int wm   = wid & 1;        // 2 m-tiles of 32 co
    const int wn   = wid >> 1;       // 4 n-tiles of 64 px
    const int q    = lane & 3;
    const int nidx = lane >> 2;
    const int w0   = blockIdx.x * TPX;
    const int h0   = blockIdx.y * TPY;
    const int n    = blockIdx.z;

    const uint32_t sa_b = (uint32_t)__cvta_generic_to_shared(s_act);
    const uint32_t sw_b = sa_b + S_ACT_HALVES*2;          // weight ring base (bytes)

    // ---- weight copy: one tap = 9216 B linear, 576 x 16B chunks ----
    const char* wsrc_base = reinterpret_cast<const char*>(wrep);
    auto copy_tap = [&](int tap) {
        const char* src = wsrc_base + tap*W_TAP_BYTES;
        uint32_t dst = sw_b + (tap % NWBUF)*W_TAP_BYTES;
        cpasync16(dst + tid*16,        src + tid*16);
        cpasync16(dst + (tid+256)*16,  src + (tid+256)*16);
        if (tid < 64) cpasync16(dst + (tid+512)*16, src + (tid+512)*16);
        asm volatile("cp.async.commit_group;");
    };

    // prologue: taps 0-3 in flight
    copy_tap(0); copy_tap(1); copy_tap(2); copy_tap(3);

    if (tid < COUT) {
        s_sum[tid] = 0.f; s_sq[tid] = 0.f;
        if (PASS == 2) { s_s[tid] = g_scale[0][tid]; s_b[tid] = g_bias[0][tid]; }
    }
    __syncthreads();   // s_s/s_b ready for PASS2 staging

    // ---- stage activation tile: 18x18 halo, fp16 pair-slots ----
    // lanes: 8 consecutive positions x 4 pair-workers -> full 32B LDG sectors.
    {
        const int pg = lane & 7;          // position in 8-group
        const int cw = (lane >> 3) & 3;   // pair worker
        int o_[6];
        unsigned mr = 0, mv = 0;
#pragma unroll
        for (int k = 0; k < 6; k++) {
            int pos = 64*k + 8*wid + pg;
            int py  = pos / 18;
            int px  = pos - py*18;
            int gh = h0 + py - 1, gw = w0 + px - 1;
            o_[k] = gh*WW + gw;
            if (pos < NPOS) {
                mr |= 1u << k;
                if ((unsigned)gh < (unsigned)HH && (unsigned)gw < (unsigned)WW)
                    mv |= 1u << k;
            }
        }
#pragma unroll
        for (int j = 0; j < 8; j++) {
            const int pp = cw + 4*j;                       // STS conflict-free
            const int c0 = ((pp >> 3) << 4) | (pp & 7);    // pair channels (c0, c0+8)
            __half2 hv[6];
            if (PASS == 1) {
                const float* p0 = x + (n*64 + c0)*HW;
                const float* p1 = p0 + 8*HW;
                float a0[6], a1[6];
#pragma unroll
                for (int k = 0; k < 6; k++) {
                    a0[k] = 0.f; a1[k] = 0.f;
                    if (mv >> k & 1) { a0[k] = p0[o_[k]]; a1[k] = p1[o_[k]]; }
                }
#pragma unroll
                for (int k = 0; k < 6; k++)
                    hv[k] = __floats2half2_rn(a0[k], a1[k]);
            } else {
                const __half2* hp = g_t1h + (n*32 + pp)*HW;
                __half2 raw[6];
#pragma unroll
                for (int k = 0; k < 6; k++) {
                    raw[k] = __floats2half2_rn(0.f, 0.f);
                    if (mv >> k & 1) raw[k] = hp[o_[k]];
                }
                const float sc0 = s_s[c0], bs0 = s_b[c0];
                const float sc1 = s_s[c0+8], bs1 = s_b[c0+8];
#pragma unroll
                for (int k = 0; k < 6; k++) {
                    float v0 = 0.f, v1 = 0.f;
                    if (mv >> k & 1) {
                        float2 f = __half22float2(raw[k]);
                        v0 = fminf(fmaxf(fmaf(f.x, sc0, bs0), -1.f), 1.f);
                        v1 = fminf(fmaxf(fmaf(f.y, sc1, bs1), -1.f), 1.f);
                    }
                    hv[k] = __floats2half2_rn(v0, v1);
                }
            }
#pragma unroll
            for (int k = 0; k < 6; k++) {
                if (mr >> k & 1) {
                    int pos = 64*k + 8*wid + pg;
                    *reinterpret_cast<__half2*>(s_act + pos*ASTR + 2*pp) = hv[k];
                }
            }
        }
    }

    float acc[2][8][4];
#pragma unroll
    for (int mt = 0; mt < 2; mt++)
#pragma unroll
        for (int nt = 0; nt < 8; nt++)
#pragma unroll
            for (int r = 0; r < 4; r++) acc[mt][nt][r] = 0.f;

    // ---- per-lane LDSM base addresses ----
    const uint32_t aA = sw_b + (((wm*32 + (lane & 15))*WSTR) + (lane >> 4)*8) * 2;
    const int px_l  = ((lane >> 4) & 1)*8 + (lane & 7);
    const int kof_l = ((lane >> 3) & 1)*8;
    const uint32_t bB = sa_b + (((wn*4)*18 + px_l)*ASTR + kof_l) * 2;

    auto compute_tap = [&](int tap) {
        const uint32_t wbuf = (uint32_t)((tap % NWBUF) * W_TAP_BYTES);
        const int dy = tap / 3, dx = tap - dy*3;
        const uint32_t tapoff = (uint32_t)((dy*18 + dx)*ASTR*2);
#pragma unroll
        for (int ch = 0; ch < 4; ch++) {
            const uint32_t ko = ch*32;
            uint32_t a[2][4];
            ldsm4(a[0][0], a[0][1], a[0][2], a[0][3], aA + wbuf + ko);
            ldsm4(a[1][0], a[1][1], a[1][2], a[1][3], aA + wbuf + ko + 16*WSTR*2);
#pragma unroll
            for (int pr = 0; pr < 4; pr++) {
                uint32_t b0, b1, b2, b3;
                ldsm4(b0, b1, b2, b3, bB + tapoff + (uint32_t)(pr*18*ASTR*2) + ko);
                mma16(acc[0][2*pr],   a[0], b0, b1);
                mma16(acc[1][2*pr],   a[1], b0, b1);
                mma16(acc[0][2*pr+1], a[0], b2, b3);
                mma16(acc[1][2*pr+1], a[1], b2, b3);
            }
        }
    };

    // ---- mainloop: 5 barrier windows of 2 taps each ----
    asm volatile("cp.async.wait_group 2;");   // taps 0,1 done
    __syncthreads();                           // + act tile visible
    compute_tap(0); compute_tap(1);
    copy_tap(4); copy_tap(5);

    asm volatile("cp.async.wait_group 2;");   // taps 0-3 done
    __syncthreads();
    compute_tap(2); compute_tap(3);
    copy_tap(6); copy_tap(7);

    asm volatile("cp.async.wait_group 2;");   // taps 0-5 done
    __syncthreads();
    compute_tap(4); compute_tap(5);
    copy_tap(8);

    asm volatile("cp.async.wait_group 1;");   // taps 0-7 done
    __syncthreads();
    compute_tap(6); compute_tap(7);

    asm volatile("cp.async.wait_group 0;");   // all done
    __syncthreads();
    compute_tap(8);

    // ---- epilogue: lane-pair shuffles -> 4 consecutive px per lane ----
    const int pxo = (q & 1) ? (2*q + 6) : (2*q);    // {0,8,4,12}: 16B aligned
#pragma unroll
    for (int mt = 0; mt < 2; mt++) {
        const int co_lo = wm*32 + mt*16 + nidx;     // bit3 == 0 always
        const int pp    = ((co_lo >> 4) << 3) | (co_lo & 7);
        float slo = 0.f, qlo = 0.f, shi = 0.f, qhi = 0.f;
#pragma unroll
        for (int ntp = 0; ntp < 4; ntp++) {
            const int py  = wn*4 + ntp;
            const int pix = (h0 + py)*WW + w0 + pxo;
            float4 o4[2];
#pragma unroll
            for (int row = 0; row < 2; row++) {
                float ax = acc[mt][2*ntp][2*row];
                float ay = acc[mt][2*ntp][2*row + 1];
                float bx = acc[mt][2*ntp+1][2*row];
                float by = acc[mt][2*ntp+1][2*row + 1];
                float sx = (q & 1) ? ax : bx;
                float sy = (q & 1) ? ay : by;
                float rx = __shfl_xor_sync(0xffffffffu, sx, 1);
                float ry = __shfl_xor_sync(0xffffffffu, sy, 1);
                o4[row] = (q & 1) ? make_float4(rx, ry, bx, by)
                                  : make_float4(ax, ay, rx, ry);
            }
            if (PASS == 2) {
                const int adr = (n*64 + co_lo)*HW + pix;
                float4 r0 = *reinterpret_cast<const float4*>(x + adr);
                float4 r1 = *reinterpret_cast<const float4*>(x + adr + 8*HW);
                o4[0].x += r0.x; o4[0].y += r0.y; o4[0].z += r0.z; o4[0].w += r0.w;
                o4[1].x += r1.x; o4[1].y += r1.y; o4[1].z += r1.z; o4[1].w += r1.w;
            }
            __half2 h4[4];
            h4[0] = __floats2half2_rn(o4[0].x, o4[1].x);
            h4[1] = __floats2half2_rn(o4[0].y, o4[1].y);
            h4[2] = __floats2half2_rn(o4[0].z, o4[1].z);
            h4[3] = __floats2half2_rn(o4[0].w, o4[1].w);
            __half2* dst = (PASS == 1) ? g_t1h : g_t2h;
            *reinterpret_cast<float4*>(dst + (n*32 + pp)*HW + pix) =
                *reinterpret_cast<const float4*>(h4);
            slo += o4[0].x + o4[0].y + o4[0].z + o4[0].w;
            qlo += o4[0].x*o4[0].x + o4[0].y*o4[0].y + o4[0].z*o4[0].z + o4[0].w*o4[0].w;
            shi += o4[1].x + o4[1].y + o4[1].z + o4[1].w;
            qhi += o4[1].x*o4[1].x + o4[1].y*o4[1].y + o4[1].z*o4[1].z + o4[1].w*o4[1].w;
        }
#pragma unroll
        for (int o = 1; o <= 2; o <<= 1) {
            slo += __shfl_xor_sync(0xffffffffu, slo, o);
            qlo += __shfl_xor_sync(0xffffffffu, qlo, o);
            shi += __shfl_xor_sync(0xffffffffu, shi, o);
            qhi += __shfl_xor_sync(0xffffffffu, qhi, o);
        }
        if (q == 0) {
            atomicAdd(&s_sum[co_lo],     slo);
            atomicAdd(&s_sq[co_lo],      qlo);
            atomicAdd(&s_sum[co_lo + 8], shi);
            atomicAdd(&s_sq[co_lo + 8],  qhi);
        }
    }
    __syncthreads();
    if (tid < COUT) {
        atomicAdd(&g_sum[PASS-1][tid], s_sum[tid]);
        atomicAdd(&g_sq[PASS-1][tid],  s_sq[tid]);
    }
}

// ---------------- fold BN stats ----------------
template<int PASS>
__global__ void finalize_kernel(const float* __restrict__ g,
                                const float* __restrict__ b) {
    int c = threadIdx.x;
    if (c < COUT) {
        const float inv = 1.f / (float)MCNT;
        float mean = g_sum[PASS-1][c] * inv;
        float var  = g_sq[PASS-1][c] * inv - mean*mean;
        float s    = g[c] * rsqrtf(var + 1e-5f);
        g_scale[PASS-1][c] = s;
        g_bias[PASS-1][c]  = b[c] - mean*s;
    }
}

// ---------------- final BN2 + hardtanh: fp16 pairs -> fp32 out ----------------
__global__ void bnact_kernel(float* __restrict__ out) {
    int i = blockIdx.x * 256 + threadIdx.x;        // float4 index into g_t2h
    if (i >= NB*32*HW/4) return;
    const int plane = i / (HW/4);                  // (n*32 + pp)
    const int px0   = (i - plane*(HW/4)) * 4;
    const int pp    = plane & 31;
    const int n     = plane >> 5;
    const int c0    = ((pp >> 3) << 4) | (pp & 7);
    const float s0  = g_scale[1][c0],   b0 = g_bias[1][c0];
    const float s1  = g_scale[1][c0+8], b1 = g_bias[1][c0+8];

    float4 raw = *reinterpret_cast<const float4*>(g_t2h + plane*HW + px0);
    const __half2* h = reinterpret_cast<const __half2*>(&raw);
    float4 o0, o1;
    float* p0 = &o0.x;
    float* p1 = &o1.x;
#pragma unroll
    for (int k = 0; k < 4; k++) {
        float2 f = __half22float2(h[k]);
        p0[k] = fminf(fmaxf(fmaf(f.x, s0, b0), -1.f), 1.f);
        p1[k] = fminf(fmaxf(fmaf(f.y, s1, b1), -1.f), 1.f);
    }
    const int adr = (n*64 + c0)*HW + px0;
    *reinterpret_cast<float4*>(out + adr)        = o0;
    *reinterpret_cast<float4*>(out + adr + 8*HW) = o1;
}

// ---------------- launch ----------------
extern "C" void kernel_launch(void* const* d_in, const int* in_sizes, int n_in,
                              void* d_out, int out_size) {
    const float* x  = (const float*)d_in[0];
    const float* w1 = (const float*)d_in[1];
    const float* g1 = (const float*)d_in[2];
    const float* b1 = (const float*)d_in[3];
    const float* w2 = (const float*)d_in[4];
    const float* g2 = (const float*)d_in[5];
    const float* b2 = (const float*)d_in[6];
    float* out = (float*)d_out;

    cudaFuncSetAttribute(conv_mma_kernel<1>,
                         cudaFuncAttributeMaxDynamicSharedMemorySize, SMEM_BYTES);
    cudaFuncSetAttribute(conv_mma_kernel<2>,
                         cudaFuncAttributeMaxDynamicSharedMemorySize, SMEM_BYTES);

    prep_kernel<<<(9*64*WSTR + 255)/256, 256>>>(w1, w2);

    dim3 cgrid(WW/TPX, HH/TPY, NB);   // (7, 7, 32)
    conv_mma_kernel<1><<<cgrid, 256, SMEM_BYTES>>>(x);
    finalize_kernel<1><<<1, 64>>>(g1, b1);

    conv_mma_kernel<2><<<cgrid, 256, SMEM_BYTES>>>(x);
    finalize_kernel<2><<<1, 64>>>(g2, b2);

    bnact_kernel<<<(NB*32*HW/4 + 255)/256, 256>>>(out);
}

// round 14
// speedup vs baseline: 1.2999x; 1.2999x over previous
#include <cuda_runtime.h>
#include <cuda_fp16.h>
#include <math.h>
#include <stdint.h>

#define CIN   64
#define COUT  64
#define HH    112
#define WW    112
#define NB    32
#define HW    (HH*WW)            // 12544
#define TOTAL (NB*COUT*HW)       // 25690112
#define MCNT  (NB*HW)            // 401408

// conv tiling: block = 64 co x 256 px (16x16), 8 warps m32xn64, fp16 mma k16
#define TPX 16
#define TPY 16
#define NPOS (18*18)             // 324 halo positions
#define ASTR 72                  // halves per pos row: LDSM conflict-free
#define WSTR 72
#define S_ACT_HALVES (NPOS*ASTR)          // 23328
#define S_W_HALVES   (64*WSTR)            // 4608 per buffer (x2)
#define SMEM_BYTES ((S_ACT_HALVES + 2*S_W_HALVES)*2)   // 65088 B -> 2 CTAs/SM

// ---------------- device scratch ----------------
// t1, t2 stored fp16, channel-pair interleaved: pair pp <-> channels (c0, c0+8),
// c0 = ((pp>>3)<<4) | (pp&7);  g_tXh[(n*32+pp)*HW + pos] = (val_c0, val_c0+8)
__device__ __half2 g_t1h[NB*32*HW];
__device__ __half2 g_t2h[NB*32*HW];
__device__ __half  g_w1[9*64*64];   // [tap][co][slot(ci)]
__device__ __half  g_w2[9*64*64];
__device__ float   g_sum[2][COUT];
__device__ float   g_sq[2][COUT];

__device__ __forceinline__ void mma16(float* d, const uint32_t* a, uint32_t b0, uint32_t b1) {
    asm volatile(
        "mma.sync.aligned.m16n8k16.row.col.f32.f16.f16.f32 "
        "{%0,%1,%2,%3}, {%4,%5,%6,%7}, {%8,%9}, {%0,%1,%2,%3};\n"
        : "+f"(d[0]), "+f"(d[1]), "+f"(d[2]), "+f"(d[3])
        : "r"(a[0]), "r"(a[1]), "r"(a[2]), "r"(a[3]), "r"(b0), "r"(b1));
}
__device__ __forceinline__ void ldsm4(uint32_t& r0, uint32_t& r1, uint32_t& r2, uint32_t& r3,
                                      uint32_t addr) {
    asm volatile("ldmatrix.sync.aligned.m8n8.x4.shared.b16 {%0,%1,%2,%3}, [%4];"
        : "=r"(r0), "=r"(r1), "=r"(r2), "=r"(r3) : "r"(addr));
}

// k slot: pairs (c, c+8) adjacent.  pp = ((ci>>4)<<3)|(ci&7), slot = 2*pp + ((ci>>3)&1)
__device__ __forceinline__ int kslot(int ci) {
    return 2*(((ci >> 4) << 3) | (ci & 7)) + ((ci >> 3) & 1);
}

// ---------------- prep: ternarize + repack(half, k-permuted) + zero stats ----
__global__ void prep_kernel(const float* __restrict__ w1,
                            const float* __restrict__ w2) {
    int idx = blockIdx.x * 256 + threadIdx.x;
    if (idx < COUT) {
        g_sum[0][idx] = 0.f; g_sum[1][idx] = 0.f;
        g_sq[0][idx]  = 0.f; g_sq[1][idx]  = 0.f;
    }
    if (idx < 9*64*64) {
        // src OIHW: idx = (co*64 + ci)*9 + t
        int co = idx / (64*9);
        int ci = (idx / 9) & 63;
        int t  = idx % 9;
        int dst = t*4096 + co*64 + kslot(ci);
        float a = w1[idx];
        g_w1[dst] = __float2half((fabsf(a) > 0.3f) ? (a > 0.f ? 1.f : -1.f) : 0.f);
        float b = w2[idx];
        g_w2[dst] = __float2half((fabsf(b) > 0.3f) ? (b > 0.f ? 1.f : -1.f) : 0.f);
    }
}

// ---------------- conv3x3 via 9 shifted 1x1 GEMMs, fp16 mma + ldmatrix ----
// PASS 1: in=x(fp32), out=g_t1h.  PASS 2: in=BN1+ht(g_t1h), out=g_t2h (conv + x).
// PASS 2 folds BN1 scale/bias in-block from g_sum[0]/g_sq[0] (no finalize kernel).
template<int PASS>
__global__ void __launch_bounds__(256, 2) conv_mma_kernel(const float* __restrict__ x,
                                                          const float* __restrict__ gam,
                                                          const float* __restrict__ bet) {
    extern __shared__ __half smem_h[];
    __half* s_act = smem_h;                       // [pos][slot] stride 72
    __half* s_wb  = smem_h + S_ACT_HALVES;        // 2 weight buffers [co][slot] stride 72
    __shared__ float s_s[COUT], s_b[COUT];
    __shared__ float s_sum[COUT], s_sq[COUT];

    const __half* wrep = (PASS == 1) ? g_w1 : g_w2;

    const int tid  = threadIdx.x;
    const int lane = tid & 31;
    const int wid  = tid >> 5;
    const int wm   = wid & 1;        // 2 m-tiles of 32 co
    const int wn   = wid >> 1;       // 4 n-tiles of 64 px
    const int q    = lane & 3;
    const int nidx = lane >> 2;
    const int w0   = blockIdx.x * TPX;
    const int h0   = blockIdx.y * TPY;
    const int n    = blockIdx.z;

    if (tid < COUT) {
        s_sum[tid] = 0.f; s_sq[tid] = 0.f;
        if (PASS == 2) {
            const float inv = 1.f / (float)MCNT;
            float mean = g_sum[0][tid] * inv;
            float var  = g_sq[0][tid] * inv - mean*mean;
            float s    = gam[tid] * rsqrtf(var + 1e-5f);
            s_s[tid] = s;
            s_b[tid] = bet[tid] - mean*s;
        }
    }
    __syncthreads();

    // prefetch tap-0 weights (2 x float4 = 16 halves / thread)
    float4 wpf[2];
#pragma unroll
    for (int k = 0; k < 2; k++)
        wpf[k] = reinterpret_cast<const float4*>(wrep)[tid + k*256];

    // ---- stage activation tile: 18x18 halo, fp16 pair-slots ----
    // lanes: 8 consecutive positions x 4 pair-workers -> full 32B LDG sectors.
    {
        const int pg = lane & 7;          // position in 8-group
        const int cw = (lane >> 3) & 3;   // pair worker
        int o_[6];
        unsigned mr = 0, mv = 0;
#pragma unroll
        for (int k = 0; k < 6; k++) {
            int pos = 64*k + 8*wid + pg;
            int py  = pos / 18;
            int px  = pos - py*18;
            int gh = h0 + py - 1, gw = w0 + px - 1;
            o_[k] = gh*WW + gw;
            if (pos < NPOS) {
                mr |= 1u << k;
                if ((unsigned)gh < (unsigned)HH && (unsigned)gw < (unsigned)WW)
                    mv |= 1u << k;
            }
        }
#pragma unroll
        for (int j = 0; j < 8; j++) {
            const int pp = cw + 4*j;                       // STS conflict-free
            const int c0 = ((pp >> 3) << 4) | (pp & 7);    // pair channels (c0, c0+8)
            __half2 hv[6];
            if (PASS == 1) {
                const float* p0 = x + (n*64 + c0)*HW;
                const float* p1 = p0 + 8*HW;
                float a0[6], a1[6];
#pragma unroll
                for (int k = 0; k < 6; k++) {
                    a0[k] = 0.f; a1[k] = 0.f;
                    if (mv >> k & 1) { a0[k] = p0[o_[k]]; a1[k] = p1[o_[k]]; }
                }
#pragma unroll
                for (int k = 0; k < 6; k++)
                    hv[k] = __floats2half2_rn(a0[k], a1[k]);
            } else {
                const __half2* hp = g_t1h + (n*32 + pp)*HW;
                __half2 raw[6];
#pragma unroll
                for (int k = 0; k < 6; k++) {
                    raw[k] = __floats2half2_rn(0.f, 0.f);
                    if (mv >> k & 1) raw[k] = hp[o_[k]];
                }
                const float sc0 = s_s[c0], bs0 = s_b[c0];
                const float sc1 = s_s[c0+8], bs1 = s_b[c0+8];
#pragma unroll
                for (int k = 0; k < 6; k++) {
                    float v0 = 0.f, v1 = 0.f;
                    if (mv >> k & 1) {
                        float2 f = __half22float2(raw[k]);
                        v0 = fminf(fmaxf(fmaf(f.x, sc0, bs0), -1.f), 1.f);
                        v1 = fminf(fmaxf(fmaf(f.y, sc1, bs1), -1.f), 1.f);
                    }
                    hv[k] = __floats2half2_rn(v0, v1);
                }
            }
#pragma unroll
            for (int k = 0; k < 6; k++) {
                if (mr >> k & 1) {
                    int pos = 64*k + 8*wid + pg;
                    *reinterpret_cast<__half2*>(s_act + pos*ASTR + 2*pp) = hv[k];
                }
            }
        }
    }

    float acc[2][8][4];
#pragma unroll
    for (int mt = 0; mt < 2; mt++)
#pragma unroll
        for (int nt = 0; nt < 8; nt++)
#pragma unroll
            for (int r = 0; r < 4; r++) acc[mt][nt][r] = 0.f;

    // ---- per-lane LDSM base addresses ----
    const uint32_t sw_b = (uint32_t)__cvta_generic_to_shared(s_wb);
    const uint32_t sa_b = (uint32_t)__cvta_generic_to_shared(s_act);
    const uint32_t aA = sw_b + (((wm*32 + (lane & 15))*WSTR) + (lane >> 4)*8) * 2;
    const int px_l  = ((lane >> 4) & 1)*8 + (lane & 7);
    const int kof_l = ((lane >> 3) & 1)*8;
    const uint32_t bB = sa_b + (((wn*4)*18 + px_l)*ASTR + kof_l) * 2;

#pragma unroll
    for (int tap = 0; tap < 9; ++tap) {
        __half* s_w = s_wb + (tap & 1)*S_W_HALVES;
        const uint32_t wbuf = (tap & 1) * (S_W_HALVES*2);
#pragma unroll
        for (int k = 0; k < 2; k++) {
            int v = tid + k*256;
            *reinterpret_cast<float4*>(s_w + (v >> 3)*WSTR + (v & 7)*8) = wpf[k];
        }
        if (tap < 8) {
            const float4* wsrc = reinterpret_cast<const float4*>(wrep + (tap+1)*4096);
#pragma unroll
            for (int k = 0; k < 2; k++) wpf[k] = wsrc[tid + k*256];
        }
        __syncthreads();   // buffer (tap&1) ready; prior reads of it finished a tap ago

        const int dy = tap / 3, dx = tap - dy*3;
        const uint32_t tapoff = (uint32_t)((dy*18 + dx)*ASTR*2);

#pragma unroll
        for (int ch = 0; ch < 4; ch++) {
            const uint32_t ko = ch*32;
            uint32_t a[2][4];
            ldsm4(a[0][0], a[0][1], a[0][2], a[0][3], aA + wbuf + ko);
            ldsm4(a[1][0], a[1][1], a[1][2], a[1][3], aA + wbuf + ko + 16*WSTR*2);
#pragma unroll
            for (int pr = 0; pr < 4; pr++) {
                uint32_t b0, b1, b2, b3;
                ldsm4(b0, b1, b2, b3, bB + tapoff + (uint32_t)(pr*18*ASTR*2) + ko);
                mma16(acc[0][2*pr],   a[0], b0, b1);
                mma16(acc[1][2*pr],   a[1], b0, b1);
                mma16(acc[0][2*pr+1], a[0], b2, b3);
                mma16(acc[1][2*pr+1], a[1], b2, b3);
            }
        }
    }

    // ---- epilogue: lane-pair shuffles -> 4 consecutive px per lane ----
    const int pxo = (q & 1) ? (2*q + 6) : (2*q);    // {0,8,4,12}: 16B aligned
#pragma unroll
    for (int mt = 0; mt < 2; mt++) {
        const int co_lo = wm*32 + mt*16 + nidx;     // bit3 == 0 always
        const int pp    = ((co_lo >> 4) << 3) | (co_lo & 7);
        float slo = 0.f, qlo = 0.f, shi = 0.f, qhi = 0.f;
#pragma unroll
        for (int ntp = 0; ntp < 4; ntp++) {
            const int py  = wn*4 + ntp;
            const int pix = (h0 + py)*WW + w0 + pxo;
            float4 o4[2];
#pragma unroll
            for (int row = 0; row < 2; row++) {
                float ax = acc[mt][2*ntp][2*row];
                float ay = acc[mt][2*ntp][2*row + 1];
                float bx = acc[mt][2*ntp+1][2*row];
                float by = acc[mt][2*ntp+1][2*row + 1];
                float sx = (q & 1) ? ax : bx;
                float sy = (q & 1) ? ay : by;
                float rx = __shfl_xor_sync(0xffffffffu, sx, 1);
                float ry = __shfl_xor_sync(0xffffffffu, sy, 1);
                o4[row] = (q & 1) ? make_float4(rx, ry, bx, by)
                                  : make_float4(ax, ay, rx, ry);
            }
            if (PASS == 2) {
                const int adr = (n*64 + co_lo)*HW + pix;
                float4 r0 = *reinterpret_cast<const float4*>(x + adr);
                float4 r1 = *reinterpret_cast<const float4*>(x + adr + 8*HW);
                o4[0].x += r0.x; o4[0].y += r0.y; o4[0].z += r0.z; o4[0].w += r0.w;
                o4[1].x += r1.x; o4[1].y += r1.y; o4[1].z += r1.z; o4[1].w += r1.w;
            }
            // pair-interleaved fp16: 4 half2 = one 16B store
            __half2 h4[4];
            h4[0] = __floats2half2_rn(o4[0].x, o4[1].x);
            h4[1] = __floats2half2_rn(o4[0].y, o4[1].y);
            h4[2] = __floats2half2_rn(o4[0].z, o4[1].z);
            h4[3] = __floats2half2_rn(o4[0].w, o4[1].w);
            __half2* dst = (PASS == 1) ? g_t1h : g_t2h;
            *reinterpret_cast<float4*>(dst + (n*32 + pp)*HW + pix) =
                *reinterpret_cast<const float4*>(h4);
            slo += o4[0].x + o4[0].y + o4[0].z + o4[0].w;
            qlo += o4[0].x*o4[0].x + o4[0].y*o4[0].y + o4[0].z*o4[0].z + o4[0].w*o4[0].w;
            shi += o4[1].x + o4[1].y + o4[1].z + o4[1].w;
            qhi += o4[1].x*o4[1].x + o4[1].y*o4[1].y + o4[1].z*o4[1].z + o4[1].w*o4[1].w;
        }
#pragma unroll
        for (int o = 1; o <= 2; o <<= 1) {
            slo += __shfl_xor_sync(0xffffffffu, slo, o);
            qlo += __shfl_xor_sync(0xffffffffu, qlo, o);
            shi += __shfl_xor_sync(0xffffffffu, shi, o);
            qhi += __shfl_xor_sync(0xffffffffu, qhi, o);
        }
        if (q == 0) {
            atomicAdd(&s_sum[co_lo],     slo);
            atomicAdd(&s_sq[co_lo],      qlo);
            atomicAdd(&s_sum[co_lo + 8], shi);
            atomicAdd(&s_sq[co_lo + 8],  qhi);
        }
    }
    __syncthreads();
    if (tid < COUT) {
        atomicAdd(&g_sum[PASS-1][tid], s_sum[tid]);
        atomicAdd(&g_sq[PASS-1][tid],  s_sq[tid]);
    }
}

// ---------------- final BN2 + hardtanh: fp16 pairs -> fp32 out ----------------
// Folds BN2 scale/bias in-block from g_sum[1]/g_sq[1] (no finalize kernel).
__global__ void bnact_kernel(float* __restrict__ out,
                             const float* __restrict__ gam,
                             const float* __restrict__ bet) {
    __shared__ float s_s[COUT], s_b[COUT];
    const int tid = threadIdx.x;
    if (tid < COUT) {
        const float inv = 1.f / (float)MCNT;
        float mean = g_sum[1][tid] * inv;
        float var  = g_sq[1][tid] * inv - mean*mean;
        float s    = gam[tid] * rsqrtf(var + 1e-5f);
        s_s[tid] = s;
        s_b[tid] = bet[tid] - mean*s;
    }
    __syncthreads();

    int i = blockIdx.x * 256 + tid;                // float4 index into g_t2h
    if (i >= NB*32*HW/4) return;
    const int plane = i / (HW/4);                  // (n*32 + pp)
    const int px0   = (i - plane*(HW/4)) * 4;
    const int pp    = plane & 31;
    const int n     = plane >> 5;
    const int c0    = ((pp >> 3) << 4) | (pp & 7);
    const float s0  = s_s[c0],   b0 = s_b[c0];
    const float s1  = s_s[c0+8], b1 = s_b[c0+8];

    float4 raw = *reinterpret_cast<const float4*>(g_t2h + plane*HW + px0);
    const __half2* h = reinterpret_cast<const __half2*>(&raw);
    float4 o0, o1;
    float* p0 = &o0.x;
    float* p1 = &o1.x;
#pragma unroll
    for (int k = 0; k < 4; k++) {
        float2 f = __half22float2(h[k]);
        p0[k] = fminf(fmaxf(fmaf(f.x, s0, b0), -1.f), 1.f);
        p1[k] = fminf(fmaxf(fmaf(f.y, s1, b1), -1.f), 1.f);
    }
    const int adr = (n*64 + c0)*HW + px0;
    *reinterpret_cast<float4*>(out + adr)        = o0;
    *reinterpret_cast<float4*>(out + adr + 8*HW) = o1;
}

// ---------------- launch ----------------
extern "C" void kernel_launch(void* const* d_in, const int* in_sizes, int n_in,
                              void* d_out, int out_size) {
    const float* x  = (const float*)d_in[0];
    const float* w1 = (const float*)d_in[1];
    const float* g1 = (const float*)d_in[2];
    const float* b1 = (const float*)d_in[3];
    const float* w2 = (const float*)d_in[4];
    const float* g2 = (const float*)d_in[5];
    const float* b2 = (const float*)d_in[6];
    float* out = (float*)d_out;

    cudaFuncSetAttribute(conv_mma_kernel<1>,
                         cudaFuncAttributeMaxDynamicSharedMemorySize, SMEM_BYTES);
    cudaFuncSetAttribute(conv_mma_kernel<2>,
                         cudaFuncAttributeMaxDynamicSharedMemorySize, SMEM_BYTES);

    prep_kernel<<<(9*64*64 + 255)/256, 256>>>(w1, w2);

    dim3 cgrid(WW/TPX, HH/TPY, NB);   // (7, 7, 32)
    conv_mma_kernel<1><<<cgrid, 256, SMEM_BYTES>>>(x, nullptr, nullptr);
    conv_mma_kernel<2><<<cgrid, 256, SMEM_BYTES>>>(x, g1, b1);
    bnact_kernel<<<(NB*32*HW/4 + 255)/256, 256>>>(out, g2, b2);
}

// round 15
// speedup vs baseline: 1.3016x; 1.0013x over previous
#include <cuda_runtime.h>
#include <cuda_fp16.h>
#include <math.h>
#include <stdint.h>

#define CIN   64
#define COUT  64
#define HH    112
#define WW    112
#define NB    32
#define HW    (HH*WW)            // 12544
#define TOTAL (NB*COUT*HW)       // 25690112
#define MCNT  (NB*HW)            // 401408

// conv tiling: block = 64 co x 256 px (16x16), 8 warps m32xn64, fp16 mma k16
#define TPX 16
#define TPY 16
#define NPOS (18*18)             // 324 halo positions
#define ASTR 72                  // halves per pos row: LDSM conflict-free
#define WSTR 72
#define S_ACT_HALVES (NPOS*ASTR)          // 23328
#define S_W_HALVES   (64*WSTR)            // 4608 per buffer (x2)
#define SMEM_BYTES ((S_ACT_HALVES + 2*S_W_HALVES)*2)   // 65088 B -> 2 CTAs/SM

// ---------------- device scratch ----------------
// t1, t2 stored fp16, channel-pair interleaved: pair pp <-> channels (c0, c0+8),
// c0 = ((pp>>3)<<4) | (pp&7);  g_tXh[(n*32+pp)*HW + pos] = (val_c0, val_c0+8)
__device__ __half2 g_t1h[NB*32*HW];
__device__ __half2 g_t2h[NB*32*HW];
__device__ __half  g_w1[9*64*64];   // [tap][co][slot(ci)]
__device__ __half  g_w2[9*64*64];
__device__ float   g_sum[2][COUT];
__device__ float   g_sq[2][COUT];

__device__ __forceinline__ void mma16(float* d, const uint32_t* a, uint32_t b0, uint32_t b1) {
    asm volatile(
        "mma.sync.aligned.m16n8k16.row.col.f32.f16.f16.f32 "
        "{%0,%1,%2,%3}, {%4,%5,%6,%7}, {%8,%9}, {%0,%1,%2,%3};\n"
        : "+f"(d[0]), "+f"(d[1]), "+f"(d[2]), "+f"(d[3])
        : "r"(a[0]), "r"(a[1]), "r"(a[2]), "r"(a[3]), "r"(b0), "r"(b1));
}
__device__ __forceinline__ void ldsm4(uint32_t& r0, uint32_t& r1, uint32_t& r2, uint32_t& r3,
                                      uint32_t addr) {
    asm volatile("ldmatrix.sync.aligned.m8n8.x4.shared.b16 {%0,%1,%2,%3}, [%4];"
        : "=r"(r0), "=r"(r1), "=r"(r2), "=r"(r3) : "r"(addr));
}

// k slot: pairs (c, c+8) adjacent.  pp = ((ci>>4)<<3)|(ci&7), slot = 2*pp + ((ci>>3)&1)
__device__ __forceinline__ int kslot(int ci) {
    return 2*(((ci >> 4) << 3) | (ci & 7)) + ((ci >> 3) & 1);
}

// ---------------- prep: ternarize + repack(half, k-permuted) + zero stats ----
__global__ void prep_kernel(const float* __restrict__ w1,
                            const float* __restrict__ w2) {
    int idx = blockIdx.x * 256 + threadIdx.x;
    if (idx < COUT) {
        g_sum[0][idx] = 0.f; g_sum[1][idx] = 0.f;
        g_sq[0][idx]  = 0.f; g_sq[1][idx]  = 0.f;
    }
    if (idx < 9*64*64) {
        // src OIHW: idx = (co*64 + ci)*9 + t
        int co = idx / (64*9);
        int ci = (idx / 9) & 63;
        int t  = idx % 9;
        int dst = t*4096 + co*64 + kslot(ci);
        float a = w1[idx];
        g_w1[dst] = __float2half((fabsf(a) > 0.3f) ? (a > 0.f ? 1.f : -1.f) : 0.f);
        float b = w2[idx];
        g_w2[dst] = __float2half((fabsf(b) > 0.3f) ? (b > 0.f ? 1.f : -1.f) : 0.f);
    }
}

// ---------------- conv3x3 via 9 shifted 1x1 GEMMs, fp16 mma + ldmatrix ----
// PASS 1: in=x(fp32), out=g_t1h.  PASS 2: in=BN1+ht(g_t1h), out=g_t2h (conv + x).
// PASS 2 folds BN1 scale/bias in-block from g_sum[0]/g_sq[0] (no finalize kernel).
template<int PASS>
__global__ void __launch_bounds__(256, 2) conv_mma_kernel(const float* __restrict__ x,
                                                          const float* __restrict__ gam,
                                                          const float* __restrict__ bet) {
    extern __shared__ __half smem_h[];
    __half* s_act = smem_h;                       // [pos][slot] stride 72
    __half* s_wb  = smem_h + S_ACT_HALVES;        // 2 weight buffers [co][slot] stride 72
    __shared__ float s_s[COUT], s_b[COUT];
    __shared__ float s_sum[COUT], s_sq[COUT];

    const __half* wrep = (PASS == 1) ? g_w1 : g_w2;

    const int tid  = threadIdx.x;
    const int lane = tid & 31;
    const int wid  = tid >> 5;
    const int wm   = wid & 1;        // 2 m-tiles of 32 co
    const int wn   = wid >> 1;       // 4 n-tiles of 64 px
    const int q    = lane & 3;
    const int nidx = lane >> 2;
    const int w0   = blockIdx.x * TPX;
    const int h0   = blockIdx.y * TPY;
    const int n    = blockIdx.z;

    if (tid < COUT) {
        s_sum[tid] = 0.f; s_sq[tid] = 0.f;
        if (PASS == 2) {
            const float inv = 1.f / (float)MCNT;
            float mean = g_sum[0][tid] * inv;
            float var  = g_sq[0][tid] * inv - mean*mean;
            float s    = gam[tid] * rsqrtf(var + 1e-5f);
            s_s[tid] = s;
            s_b[tid] = bet[tid] - mean*s;
        }
    }
    __syncthreads();

    // prefetch tap-0 weights (2 x float4 = 16 halves / thread)
    float4 wpf[2];
#pragma unroll
    for (int k = 0; k < 2; k++)
        wpf[k] = reinterpret_cast<const float4*>(wrep)[tid + k*256];

    // ---- stage activation tile: 18x18 halo, fp16 pair-slots ----
    // lanes: 8 consecutive positions x 4 pair-workers -> full 32B LDG sectors.
    {
        const int pg = lane & 7;          // position in 8-group
        const int cw = (lane >> 3) & 3;   // pair worker
        int o_[6];
        unsigned mr = 0, mv = 0;
#pragma unroll
        for (int k = 0; k < 6; k++) {
            int pos = 64*k + 8*wid + pg;
            int py  = pos / 18;
            int px  = pos - py*18;
            int gh = h0 + py - 1, gw = w0 + px - 1;
            o_[k] = gh*WW + gw;
            if (pos < NPOS) {
                mr |= 1u << k;
                if ((unsigned)gh < (unsigned)HH && (unsigned)gw < (unsigned)WW)
                    mv |= 1u << k;
            }
        }
#pragma unroll
        for (int j = 0; j < 8; j++) {
            const int pp = cw + 4*j;                       // STS conflict-free
            const int c0 = ((pp >> 3) << 4) | (pp & 7);    // pair channels (c0, c0+8)
            __half2 hv[6];
            if (PASS == 1) {
                const float* p0 = x + (n*64 + c0)*HW;
                const float* p1 = p0 + 8*HW;
                float a0[6], a1[6];
#pragma unroll
                for (int k = 0; k < 6; k++) {
                    a0[k] = 0.f; a1[k] = 0.f;
                    if (mv >> k & 1) { a0[k] = p0[o_[k]]; a1[k] = p1[o_[k]]; }
                }
#pragma unroll
                for (int k = 0; k < 6; k++)
                    hv[k] = __floats2half2_rn(a0[k], a1[k]);
            } else {
                const __half2* hp = g_t1h + (n*32 + pp)*HW;
                __half2 raw[6];
#pragma unroll
                for (int k = 0; k < 6; k++) {
                    raw[k] = __floats2half2_rn(0.f, 0.f);
                    if (mv >> k & 1) raw[k] = hp[o_[k]];
                }
                const float sc0 = s_s[c0], bs0 = s_b[c0];
                const float sc1 = s_s[c0+8], bs1 = s_b[c0+8];
#pragma unroll
                for (int k = 0; k < 6; k++) {
                    float v0 = 0.f, v1 = 0.f;
                    if (mv >> k & 1) {
                        float2 f = __half22float2(raw[k]);
                        v0 = fminf(fmaxf(fmaf(f.x, sc0, bs0), -1.f), 1.f);
                        v1 = fminf(fmaxf(fmaf(f.y, sc1, bs1), -1.f), 1.f);
                    }
                    hv[k] = __floats2half2_rn(v0, v1);
                }
            }
#pragma unroll
            for (int k = 0; k < 6; k++) {
                if (mr >> k & 1) {
                    int pos = 64*k + 8*wid + pg;
                    *reinterpret_cast<__half2*>(s_act + pos*ASTR + 2*pp) = hv[k];
                }
            }
        }
    }

    float acc[2][8][4];
#pragma unroll
    for (int mt = 0; mt < 2; mt++)
#pragma unroll
        for (int nt = 0; nt < 8; nt++)
#pragma unroll
            for (int r = 0; r < 4; r++) acc[mt][nt][r] = 0.f;

    // ---- per-lane LDSM base addresses ----
    const uint32_t sw_b = (uint32_t)__cvta_generic_to_shared(s_wb);
    const uint32_t sa_b = (uint32_t)__cvta_generic_to_shared(s_act);
    const uint32_t aA = sw_b + (((wm*32 + (lane & 15))*WSTR) + (lane >> 4)*8) * 2;
    const int px_l  = ((lane >> 4) & 1)*8 + (lane & 7);
    const int kof_l = ((lane >> 3) & 1)*8;
    const uint32_t bB = sa_b + (((wn*4)*18 + px_l)*ASTR + kof_l) * 2;

#pragma unroll
    for (int tap = 0; tap < 9; ++tap) {
        __half* s_w = s_wb + (tap & 1)*S_W_HALVES;
        const uint32_t wbuf = (tap & 1) * (S_W_HALVES*2);
#pragma unroll
        for (int k = 0; k < 2; k++) {
            int v = tid + k*256;
            *reinterpret_cast<float4*>(s_w + (v >> 3)*WSTR + (v & 7)*8) = wpf[k];
        }
        if (tap < 8) {
            const float4* wsrc = reinterpret_cast<const float4*>(wrep + (tap+1)*4096);
#pragma unroll
            for (int k = 0; k < 2; k++) wpf[k] = wsrc[tid + k*256];
        }
        __syncthreads();   // buffer (tap&1) ready; prior reads of it finished a tap ago

        const int dy = tap / 3, dx = tap - dy*3;
        const uint32_t tapoff = (uint32_t)((dy*18 + dx)*ASTR*2);

#pragma unroll
        for (int ch = 0; ch < 4; ch++) {
            const uint32_t ko = ch*32;
            uint32_t a[2][4];
            ldsm4(a[0][0], a[0][1], a[0][2], a[0][3], aA + wbuf + ko);
            ldsm4(a[1][0], a[1][1], a[1][2], a[1][3], aA + wbuf + ko + 16*WSTR*2);
#pragma unroll
            for (int pr = 0; pr < 4; pr++) {
                uint32_t b0, b1, b2, b3;
                ldsm4(b0, b1, b2, b3, bB + tapoff + (uint32_t)(pr*18*ASTR*2) + ko);
                mma16(acc[0][2*pr],   a[0], b0, b1);
                mma16(acc[1][2*pr],   a[1], b0, b1);
                mma16(acc[0][2*pr+1], a[0], b2, b3);
                mma16(acc[1][2*pr+1], a[1], b2, b3);
            }
        }
    }

    // ---- epilogue: lane-pair shuffles -> 4 consecutive px per lane ----
    const int pxo = (q & 1) ? (2*q + 6) : (2*q);    // {0,8,4,12}: 16B aligned
#pragma unroll
    for (int mt = 0; mt < 2; mt++) {
        const int co_lo = wm*32 + mt*16 + nidx;     // bit3 == 0 always
        const int pp    = ((co_lo >> 4) << 3) | (co_lo & 7);
        float slo = 0.f, qlo = 0.f, shi = 0.f, qhi = 0.f;
#pragma unroll
        for (int ntp = 0; ntp < 4; ntp++) {
            const int py  = wn*4 + ntp;
            const int pix = (h0 + py)*WW + w0 + pxo;
            float4 o4[2];
#pragma unroll
            for (int row = 0; row < 2; row++) {
                float ax = acc[mt][2*ntp][2*row];
                float ay = acc[mt][2*ntp][2*row + 1];
                float bx = acc[mt][2*ntp+1][2*row];
                float by = acc[mt][2*ntp+1][2*row + 1];
                float sx = (q & 1) ? ax : bx;
                float sy = (q & 1) ? ay : by;
                float rx = __shfl_xor_sync(0xffffffffu, sx, 1);
                float ry = __shfl_xor_sync(0xffffffffu, sy, 1);
                o4[row] = (q & 1) ? make_float4(rx, ry, bx, by)
                                  : make_float4(ax, ay, rx, ry);
            }
            if (PASS == 2) {
                const int adr = (n*64 + co_lo)*HW + pix;
                float4 r0 = *reinterpret_cast<const float4*>(x + adr);
                float4 r1 = *reinterpret_cast<const float4*>(x + adr + 8*HW);
                o4[0].x += r0.x; o4[0].y += r0.y; o4[0].z += r0.z; o4[0].w += r0.w;
                o4[1].x += r1.x; o4[1].y += r1.y; o4[1].z += r1.z; o4[1].w += r1.w;
            }
            // pair-interleaved fp16: 4 half2 = one 16B store
            __half2 h4[4];
            h4[0] = __floats2half2_rn(o4[0].x, o4[1].x);
            h4[1] = __floats2half2_rn(o4[0].y, o4[1].y);
            h4[2] = __floats2half2_rn(o4[0].z, o4[1].z);
            h4[3] = __floats2half2_rn(o4[0].w, o4[1].w);
            __half2* dst = (PASS == 1) ? g_t1h : g_t2h;
            *reinterpret_cast<float4*>(dst + (n*32 + pp)*HW + pix) =
                *reinterpret_cast<const float4*>(h4);
            slo += o4[0].x + o4[0].y + o4[0].z + o4[0].w;
            qlo += o4[0].x*o4[0].x + o4[0].y*o4[0].y + o4[0].z*o4[0].z + o4[0].w*o4[0].w;
            shi += o4[1].x + o4[1].y + o4[1].z + o4[1].w;
            qhi += o4[1].x*o4[1].x + o4[1].y*o4[1].y + o4[1].z*o4[1].z + o4[1].w*o4[1].w;
        }
#pragma unroll
        for (int o = 1; o <= 2; o <<= 1) {
            slo += __shfl_xor_sync(0xffffffffu, slo, o);
            qlo += __shfl_xor_sync(0xffffffffu, qlo, o);
            shi += __shfl_xor_sync(0xffffffffu, shi, o);
            qhi += __shfl_xor_sync(0xffffffffu, qhi, o);
        }
        if (q == 0) {
            atomicAdd(&s_sum[co_lo],     slo);
            atomicAdd(&s_sq[co_lo],      qlo);
            atomicAdd(&s_sum[co_lo + 8], shi);
            atomicAdd(&s_sq[co_lo + 8],  qhi);
        }
    }
    __syncthreads();
    if (tid < COUT) {
        atomicAdd(&g_sum[PASS-1][tid], s_sum[tid]);
        atomicAdd(&g_sq[PASS-1][tid],  s_sq[tid]);
    }
}

// ---------------- final BN2 + hardtanh: fp16 pairs -> fp32 out ----------------
// Folds BN2 scale/bias in-block from g_sum[1]/g_sq[1] (no finalize kernel).
__global__ void bnact_kernel(float* __restrict__ out,
                             const float* __restrict__ gam,
                             const float* __restrict__ bet) {
    __shared__ float s_s[COUT], s_b[COUT];
    const int tid = threadIdx.x;
    if (tid < COUT) {
        const float inv = 1.f / (float)MCNT;
        float mean = g_sum[1][tid] * inv;
        float var  = g_sq[1][tid] * inv - mean*mean;
        float s    = gam[tid] * rsqrtf(var + 1e-5f);
        s_s[tid] = s;
        s_b[tid] = bet[tid] - mean*s;
    }
    __syncthreads();

    int i = blockIdx.x * 256 + tid;                // float4 index into g_t2h
    if (i >= NB*32*HW/4) return;
    const int plane = i / (HW/4);                  // (n*32 + pp)
    const int px0   = (i - plane*(HW/4)) * 4;
    const int pp    = plane & 31;
    const int n     = plane >> 5;
    const int c0    = ((pp >> 3) << 4) | (pp & 7);
    const float s0  = s_s[c0],   b0 = s_b[c0];
    const float s1  = s_s[c0+8], b1 = s_b[c0+8];

    float4 raw = *reinterpret_cast<const float4*>(g_t2h + plane*HW + px0);
    const __half2* h = reinterpret_cast<const __half2*>(&raw);
    float4 o0, o1;
    float* p0 = &o0.x;
    float* p1 = &o1.x;
#pragma unroll
    for (int k = 0; k < 4; k++) {
        float2 f = __half22float2(h[k]);
        p0[k] = fminf(fmaxf(fmaf(f.x, s0, b0), -1.f), 1.f);
        p1[k] = fminf(fmaxf(fmaf(f.y, s1, b1), -1.f), 1.f);
    }
    const int adr = (n*64 + c0)*HW + px0;
    *reinterpret_cast<float4*>(out + adr)        = o0;
    *reinterpret_cast<float4*>(out + adr + 8*HW) = o1;
}

// ---------------- launch ----------------
extern "C" void kernel_launch(void* const* d_in, const int* in_sizes, int n_in,
                              void* d_out, int out_size) {
    const float* x  = (const float*)d_in[0];
    const float* w1 = (const float*)d_in[1];
    const float* g1 = (const float*)d_in[2];
    const float* b1 = (const float*)d_in[3];
    const float* w2 = (const float*)d_in[4];
    const float* g2 = (const float*)d_in[5];
    const float* b2 = (const float*)d_in[6];
    float* out = (float*)d_out;

    cudaFuncSetAttribute(conv_mma_kernel<1>,
                         cudaFuncAttributeMaxDynamicSharedMemorySize, SMEM_BYTES);
    cudaFuncSetAttribute(conv_mma_kernel<2>,
                         cudaFuncAttributeMaxDynamicSharedMemorySize, SMEM_BYTES);

    prep_kernel<<<(9*64*64 + 255)/256, 256>>>(w1, w2);

    dim3 cgrid(WW/TPX, HH/TPY, NB);   // (7, 7, 32)
    conv_mma_kernel<1><<<cgrid, 256, SMEM_BYTES>>>(x, nullptr, nullptr);
    conv_mma_kernel<2><<<cgrid, 256, SMEM_BYTES>>>(x, g1, b1);
    bnact_kernel<<<(NB*32*HW/4 + 255)/256, 256>>>(out, g2, b2);
}